// round 13
// baseline (speedup 1.0000x reference)
#include <cuda_runtime.h>
#include <cstdint>

// Problem: BinarizedNetwork_91139206021329   (bit-exact vs XLA:CPU reference)
// Layer 1: fp32 STRICT sequential-k FMA GEMM using packed fma.rn.f32x2
//          (each lane is an IEEE fp32 RN FMA -> bit-identical to scalar FFMA),
//          prefetch-overlapped; STRICT sequential-row mean (spread 64 blocks).
// Layers 2..4: exact integer binary GEMMs (XOR+popcount) with exact
//          jnp.sign(0)=0 handling via zero-lists + fix-up kernels.

#define N_IMG   16
#define F_DIM   512
#define T_DIM   512
#define H_DIM   2048
#define R_ROWS  8192          // N_IMG * T_DIM
#define KW      64            // H_DIM / 32 packed words
#define KWPAD   68            // padded smem row stride (words)
#define EPS_BN  1e-5f
#define MAXZ    1024          // max tracked sign(0) events per boundary

// packed dual fp32 FMA: d = a*b + d per 32-bit lane (RN, fused). Blackwell-only.
#define FFMA2(d, a, b) \
    asm("fma.rn.f32x2 %0, %1, %2, %0;" : "+l"(d) : "l"(a), "l"(b))

// ------------------------- scratch (device globals; no allocation) ----------
__device__ float    g_H1 [R_ROWS * H_DIM];    // layer-1 pre-BN activations
__device__ int      g_H2 [R_ROWS * H_DIM];
__device__ int      g_H3 [R_ROWS * H_DIM];
__device__ unsigned g_B1 [R_ROWS * KW];
__device__ unsigned g_B2 [R_ROWS * KW];
__device__ unsigned g_B3 [R_ROWS * KW];
__device__ unsigned g_W2b[H_DIM * KW];
__device__ unsigned g_W3b[H_DIM * KW];
__device__ unsigned g_W4b[F_DIM * KW];
__device__ float    g_mu [H_DIM];
__device__ float    g_rs [H_DIM];
__device__ int      g_nz1, g_nz2, g_nz3;      // zero-event counters
__device__ int2     g_z1[MAXZ], g_z2[MAXZ], g_z3[MAXZ];   // (row, col)

// ------------------------- misc ----------------------------------------------
__global__ void k_reset() { g_nz1 = 0; g_nz2 = 0; g_nz3 = 0; }

// pack one 32-float chunk per warp: bit set <=> weight < 0 (sign == -1)
__global__ void k_pack_w(const float* __restrict__ W, unsigned* __restrict__ B,
                         int total_words) {
    int gw   = (blockIdx.x * blockDim.x + threadIdx.x) >> 5;
    int lane = threadIdx.x & 31;
    if (gw < total_words) {
        float w = W[gw * 32 + lane];
        unsigned bits = __ballot_sync(0xffffffffu, w < 0.f);
        if (lane == 0) B[gw] = bits;
    }
}

__device__ __forceinline__ float signf_ref(float w) {
    return (w > 0.f) ? 1.f : ((w < 0.f) ? -1.f : 0.f);
}

// ------------------------- layer-1 fp32 GEMM --------------------------------
// H1[r, j] = sum_f x[n, f, t] * sign(W1[j, f]),  r = n*512 + t
// ONE accumulator per output, k strictly ascending 0..511; every FMA is an
// IEEE fp32 RN fused op (f32x2 lanes are independent) -> bit-exact vs scalar.
// A-tile staged DUPLICATED (As2[kk][2m]=As2[kk][2m+1]) so {a,a} packs come
// from LDS.128 directly; B-pairs load as ulonglong2 (pre-packed f32x2).
__global__ __launch_bounds__(256) void k_gemm1(const float* __restrict__ x,
                                               const float* __restrict__ W1) {
    __shared__ float As2[16][256];   // duplicated columns
    __shared__ float Bs [16][128];
    const int tid = threadIdx.x;
    const int bm  = blockIdx.y * 128;
    const int bn  = blockIdx.x * 128;
    const float* xb = x + (bm >> 9) * (F_DIM * T_DIM) + (bm & 511);
    const int tx = tid & 15, ty = tid >> 4;

    // staging assignments (fixed per thread)
    const int sa_k = tid >> 7;           // 0..1
    const int sa_m = tid & 127;
    const int sb_j = tid >> 2;           // 0..63 (two j's: +0, +64)
    const int sb_f = (tid & 3) * 4;

    float  ra[8];
    float4 rb[2];

    // ---- load tile k0 = 0 into regs ----
#pragma unroll
    for (int p = 0; p < 8; p++)
        ra[p] = xb[(sa_k + 2 * p) * T_DIM + sa_m];
#pragma unroll
    for (int p = 0; p < 2; p++)
        rb[p] = *reinterpret_cast<const float4*>(
            &W1[(size_t)(bn + sb_j + 64 * p) * F_DIM + sb_f]);

    // ---- store tile 0 (A duplicated, sign(W1) folded into B) ----
#pragma unroll
    for (int p = 0; p < 8; p++)
        *reinterpret_cast<float2*>(&As2[sa_k + 2 * p][2 * sa_m]) =
            make_float2(ra[p], ra[p]);
#pragma unroll
    for (int p = 0; p < 2; p++) {
        int j = sb_j + 64 * p;
        Bs[sb_f + 0][j] = signf_ref(rb[p].x);
        Bs[sb_f + 1][j] = signf_ref(rb[p].y);
        Bs[sb_f + 2][j] = signf_ref(rb[p].z);
        Bs[sb_f + 3][j] = signf_ref(rb[p].w);
    }
    __syncthreads();

    __align__(16) unsigned long long acc2[8][4];   // [row][colpair], lo = even col
#pragma unroll
    for (int i = 0; i < 8; i++)
#pragma unroll
        for (int j = 0; j < 4; j++) acc2[i][j] = 0ull;

    for (int k0 = 16; k0 <= F_DIM; k0 += 16) {
        const bool more = (k0 < F_DIM);
        if (more) {   // prefetch next tile (overlaps compute)
#pragma unroll
            for (int p = 0; p < 8; p++)
                ra[p] = xb[(k0 + sa_k + 2 * p) * T_DIM + sa_m];
#pragma unroll
            for (int p = 0; p < 2; p++)
                rb[p] = *reinterpret_cast<const float4*>(
                    &W1[(size_t)(bn + sb_j + 64 * p) * F_DIM + k0 + sb_f]);
        }
#pragma unroll
        for (int kk = 0; kk < 16; kk++) {
            unsigned long long aa[4 * 2], bb[4];
            {
                ulonglong2 t;
                t = *reinterpret_cast<const ulonglong2*>(&As2[kk][ty * 16 + 0]);
                aa[0] = t.x; aa[1] = t.y;
                t = *reinterpret_cast<const ulonglong2*>(&As2[kk][ty * 16 + 4]);
                aa[2] = t.x; aa[3] = t.y;
                t = *reinterpret_cast<const ulonglong2*>(&As2[kk][ty * 16 + 8]);
                aa[4] = t.x; aa[5] = t.y;
                t = *reinterpret_cast<const ulonglong2*>(&As2[kk][ty * 16 + 12]);
                aa[6] = t.x; aa[7] = t.y;
                t = *reinterpret_cast<const ulonglong2*>(&Bs[kk][tx * 8 + 0]);
                bb[0] = t.x; bb[1] = t.y;
                t = *reinterpret_cast<const ulonglong2*>(&Bs[kk][tx * 8 + 4]);
                bb[2] = t.x; bb[3] = t.y;
            }
#pragma unroll
            for (int i = 0; i < 8; i++)
#pragma unroll
                for (int jp = 0; jp < 4; jp++)
                    FFMA2(acc2[i][jp], aa[i], bb[jp]);
        }
        if (more) {
            __syncthreads();
#pragma unroll
            for (int p = 0; p < 8; p++)
                *reinterpret_cast<float2*>(&As2[sa_k + 2 * p][2 * sa_m]) =
                    make_float2(ra[p], ra[p]);
#pragma unroll
            for (int p = 0; p < 2; p++) {
                int j = sb_j + 64 * p;
                Bs[sb_f + 0][j] = signf_ref(rb[p].x);
                Bs[sb_f + 1][j] = signf_ref(rb[p].y);
                Bs[sb_f + 2][j] = signf_ref(rb[p].z);
                Bs[sb_f + 3][j] = signf_ref(rb[p].w);
            }
            __syncthreads();
        }
    }

#pragma unroll
    for (int i = 0; i < 8; i++) {
        float4* dst = reinterpret_cast<float4*>(
            &g_H1[(size_t)(bm + ty * 8 + i) * H_DIM + bn + tx * 8]);
        dst[0] = reinterpret_cast<const float4*>(&acc2[i][0])[0];
        dst[1] = reinterpret_cast<const float4*>(&acc2[i][0])[1];
    }
}

// ------------------------- BN stats (layer 1, fp32) ---------------------------
// STRICT sequential accumulation over rows 0..8191 per column (bit-matches
// XLA:CPU column-reduce). Per-thread work identical regardless of block
// partitioning; 64 blocks x 32 threads spreads the sweep across more SMs.
__global__ __launch_bounds__(32) void k_stats_f_seq() {
    int c = blockIdx.x * blockDim.x + threadIdx.x;   // 0..2047
    float s = 0.f, q = 0.f;
    for (int r = 0; r < R_ROWS; r++) {
        float h = g_H1[(size_t)r * H_DIM + c];
        s += h;
        q = fmaf(h, h, q);
    }
    float mu  = s * (1.0f / R_ROWS);
    float var = q * (1.0f / R_ROWS) - mu * mu;
    g_mu[c] = mu;
    g_rs[c] = rsqrtf(fmaxf(var, 0.f) + EPS_BN);
}

// integer activations: exact sums (|partial| <= 2^24) -> mu bit-exact.
__global__ __launch_bounds__(1024) void k_stats_i(const int* __restrict__ H) {
    __shared__ int       s_sum[1024];
    __shared__ long long s_sq [1024];
    const int tid = threadIdx.x;
    const int c  = blockIdx.x * 32 + (tid & 31);
    const int ry = tid >> 5;
    int s = 0; long long q = 0;
    for (int i = 0; i < R_ROWS / 32; i++) {
        int h = H[(size_t)(i * 32 + ry) * H_DIM + c];
        s += h; q += (long long)h * h;
    }
    s_sum[tid] = s; s_sq[tid] = q;
    __syncthreads();
    if (ry == 0) {
        for (int k = 1; k < 32; k++) {
            s += s_sum[tid + 32 * k];
            q += s_sq [tid + 32 * k];
        }
        float  mu  = (float)s * (1.0f / R_ROWS);
        double var = (double)q * (1.0 / R_ROWS) - (double)mu * (double)mu;
        g_mu[c] = mu;
        g_rs[c] = rsqrtf(fmaxf((float)var, 0.f) + EPS_BN);
    }
}

// ------------------------- BN + sign + bit-pack (+ zero detect) ---------------
__global__ __launch_bounds__(256) void k_pack_f(unsigned* __restrict__ B,
        const float* __restrict__ gg, const float* __restrict__ bb,
        int* __restrict__ nz, int2* __restrict__ zl) {
    int gw   = (blockIdx.x * blockDim.x + threadIdx.x) >> 5;
    int lane = threadIdx.x & 31;
    if (gw < R_ROWS * KW) {
        int c = (gw & 63) * 32 + lane;
        float h = g_H1[(size_t)(gw >> 6) * H_DIM + c];
        float v = fmaf(gg[c], (h - g_mu[c]) * g_rs[c], bb[c]);
        unsigned bits = __ballot_sync(0xffffffffu, v < 0.f);
        if (v == 0.0f) {
            int idx = atomicAdd(nz, 1);
            if (idx < MAXZ) zl[idx] = make_int2(gw >> 6, c);
        }
        if (lane == 0) B[gw] = bits;
    }
}

__global__ __launch_bounds__(256) void k_pack_i(const int* __restrict__ H,
        unsigned* __restrict__ B,
        const float* __restrict__ gg, const float* __restrict__ bb,
        int* __restrict__ nz, int2* __restrict__ zl) {
    int gw   = (blockIdx.x * blockDim.x + threadIdx.x) >> 5;
    int lane = threadIdx.x & 31;
    if (gw < R_ROWS * KW) {
        int c = (gw & 63) * 32 + lane;
        float h = (float)H[(size_t)(gw >> 6) * H_DIM + c];
        float v = fmaf(gg[c], (h - g_mu[c]) * g_rs[c], bb[c]);
        unsigned bits = __ballot_sync(0xffffffffu, v < 0.f);
        if (v == 0.0f) {
            int idx = atomicAdd(nz, 1);
            if (idx < MAXZ) zl[idx] = make_int2(gw >> 6, c);
        }
        if (lane == 0) B[gw] = bits;
    }
}

// ------------------------- zero fix-ups ---------------------------------------
// A zero at (r, p) was packed as +1; true contribution is 0:
// H[r][o] += (w_bit ? +1 : -1). Exact integers; order-free.
__global__ __launch_bounds__(128) void k_fixH(const int2* __restrict__ zl,
        const int* __restrict__ nz, const unsigned* __restrict__ Wb,
        int* __restrict__ H, int Ncols) {
    int o = blockIdx.x * blockDim.x + threadIdx.x;
    if (o >= Ncols) return;
    int n = *nz; if (n > MAXZ) n = MAXZ;
    for (int i = 0; i < n; i++) {
        int r = zl[i].x, p = zl[i].y;
        unsigned w = Wb[(size_t)o * KW + (p >> 5)];
        H[(size_t)r * Ncols + o] += ((w >> (p & 31)) & 1) ? 1 : -1;
    }
}

__global__ __launch_bounds__(128) void k_fixOut(const int2* __restrict__ zl,
        const int* __restrict__ nz, const unsigned* __restrict__ Wb,
        float* __restrict__ out, const float* __restrict__ scale) {
    int o = blockIdx.x * blockDim.x + threadIdx.x;
    if (o >= F_DIM) return;
    int n = *nz; if (n > MAXZ) n = MAXZ;
    for (int i = 0; i < n; i++) {
        int r = zl[i].x, p = zl[i].y;
        int nimg = r >> 9, t = r & 511;
        unsigned w = Wb[(size_t)o * KW + (p >> 5)];
        float d = (((w >> (p & 31)) & 1) ? 1.f : -1.f) * scale[o];
        out[(size_t)nimg * (F_DIM * T_DIM) + (size_t)o * T_DIM + t] += d;
    }
}

// ------------------------- binary GEMM (popcount) ----------------------------
// dot(K=2048) = 2048 - 2*popc(a XOR b). 64x64 tile, full K staged in smem.
template <bool FINAL>
__global__ __launch_bounds__(256) void k_bingemm(
        const unsigned* __restrict__ A, const unsigned* __restrict__ Wb,
        int* __restrict__ Hout, int Ncols,
        const float* __restrict__ scale, float* __restrict__ out) {
    __shared__ unsigned As[64][KWPAD];
    __shared__ unsigned Bs[64][KWPAD];
    const int tid = threadIdx.x;
    const int bm  = blockIdx.y * 64;
    const int bn  = blockIdx.x * 64;

    {
        int m = tid >> 2;
        int q = tid & 3;
        const uint4* srcA = reinterpret_cast<const uint4*>(A  + (size_t)(bm + m) * KW);
        const uint4* srcB = reinterpret_cast<const uint4*>(Wb + (size_t)(bn + m) * KW);
#pragma unroll
        for (int p = 0; p < 4; p++) {
            uint4 v = srcA[q + 4 * p];
            int w = (q + 4 * p) * 4;
            As[w + 0][m] = v.x; As[w + 1][m] = v.y;
            As[w + 2][m] = v.z; As[w + 3][m] = v.w;
        }
#pragma unroll
        for (int p = 0; p < 4; p++) {
            uint4 v = srcB[q + 4 * p];
            int w = (q + 4 * p) * 4;
            Bs[w + 0][m] = v.x; Bs[w + 1][m] = v.y;
            Bs[w + 2][m] = v.z; Bs[w + 3][m] = v.w;
        }
    }
    __syncthreads();

    const int tx = tid & 15, ty = tid >> 4;
    const int m0 = ty * 4, n0 = tx * 4;
    int acc[4][4];
#pragma unroll
    for (int i = 0; i < 4; i++)
#pragma unroll
        for (int j = 0; j < 4; j++) acc[i][j] = 0;

#pragma unroll 4
    for (int kk = 0; kk < 64; kk += 2) {
        uint4 av0 = *reinterpret_cast<const uint4*>(&As[kk + 0][m0]);
        uint4 bv0 = *reinterpret_cast<const uint4*>(&Bs[kk + 0][n0]);
        uint4 av1 = *reinterpret_cast<const uint4*>(&As[kk + 1][m0]);
        uint4 bv1 = *reinterpret_cast<const uint4*>(&Bs[kk + 1][n0]);
        unsigned a0[4] = {av0.x, av0.y, av0.z, av0.w};
        unsigned b0[4] = {bv0.x, bv0.y, bv0.z, bv0.w};
        unsigned a1[4] = {av1.x, av1.y, av1.z, av1.w};
        unsigned b1[4] = {bv1.x, bv1.y, bv1.z, bv1.w};
#pragma unroll
        for (int i = 0; i < 4; i++)
#pragma unroll
            for (int j = 0; j < 4; j++)
                acc[i][j] += __popc(a0[i] ^ b0[j]) + __popc(a1[i] ^ b1[j]);
    }

    if (!FINAL) {
#pragma unroll
        for (int i = 0; i < 4; i++) {
            int4 v = make_int4(H_DIM - 2 * acc[i][0], H_DIM - 2 * acc[i][1],
                               H_DIM - 2 * acc[i][2], H_DIM - 2 * acc[i][3]);
            *reinterpret_cast<int4*>(
                &Hout[(size_t)(bm + m0 + i) * Ncols + bn + n0]) = v;
        }
    } else {
#pragma unroll
        for (int i = 0; i < 4; i++) {
            int r = bm + m0 + i;
            int nimg = r >> 9, t = r & 511;
#pragma unroll
            for (int j = 0; j < 4; j++) {
                int o = bn + n0 + j;
                out[(size_t)nimg * (F_DIM * T_DIM) + (size_t)o * T_DIM + t] =
                    (float)(H_DIM - 2 * acc[i][j]) * scale[o];
            }
        }
    }
}

// ------------------------- launch --------------------------------------------
extern "C" void kernel_launch(void* const* d_in, const int* in_sizes, int n_in,
                              void* d_out, int out_size) {
    (void)in_sizes; (void)n_in; (void)out_size;
    const float* x     = (const float*)d_in[0];
    // d_in[1] = conv_w : dead computation in the reference, skipped.
    const float* W1    = (const float*)d_in[2];
    const float* g1    = (const float*)d_in[3];
    const float* b1    = (const float*)d_in[4];
    const float* W2    = (const float*)d_in[5];
    const float* g2    = (const float*)d_in[6];
    const float* b2    = (const float*)d_in[7];
    const float* W3    = (const float*)d_in[8];
    const float* g3    = (const float*)d_in[9];
    const float* b3    = (const float*)d_in[10];
    const float* W4    = (const float*)d_in[11];
    const float* scale = (const float*)d_in[12];
    float* out = (float*)d_out;

    void *pW2b, *pW3b, *pW4b, *pH2, *pH3, *pB1, *pB2, *pB3;
    void *pnz1, *pnz2, *pnz3, *pz1, *pz2, *pz3;
    cudaGetSymbolAddress(&pW2b, g_W2b);
    cudaGetSymbolAddress(&pW3b, g_W3b);
    cudaGetSymbolAddress(&pW4b, g_W4b);
    cudaGetSymbolAddress(&pH2,  g_H2);
    cudaGetSymbolAddress(&pH3,  g_H3);
    cudaGetSymbolAddress(&pB1,  g_B1);
    cudaGetSymbolAddress(&pB2,  g_B2);
    cudaGetSymbolAddress(&pB3,  g_B3);
    cudaGetSymbolAddress(&pnz1, g_nz1);
    cudaGetSymbolAddress(&pnz2, g_nz2);
    cudaGetSymbolAddress(&pnz3, g_nz3);
    cudaGetSymbolAddress(&pz1,  g_z1);
    cudaGetSymbolAddress(&pz2,  g_z2);
    cudaGetSymbolAddress(&pz3,  g_z3);

    k_reset<<<1, 1>>>();

    // weight prep (sign(W1) folded into k_gemm1's staging)
    k_pack_w<<<(H_DIM * KW * 32) / 256, 256>>>(W2, (unsigned*)pW2b, H_DIM * KW);
    k_pack_w<<<(H_DIM * KW * 32) / 256, 256>>>(W3, (unsigned*)pW3b, H_DIM * KW);
    k_pack_w<<<(F_DIM * KW * 32) / 256, 256>>>(W4, (unsigned*)pW4b, F_DIM * KW);

    // layer 1: fp32 GEMM (f32x2, prefetch) -> sequential mean -> sign/pack
    k_gemm1<<<dim3(H_DIM / 128, R_ROWS / 128), 256>>>(x, W1);
    k_stats_f_seq<<<H_DIM / 32, 32>>>();
    k_pack_f<<<(R_ROWS * KW * 32) / 256, 256>>>((unsigned*)pB1, g1, b1,
                                                (int*)pnz1, (int2*)pz1);

    // layer 2
    k_bingemm<false><<<dim3(H_DIM / 64, R_ROWS / 64), 256>>>(
        (const unsigned*)pB1, (const unsigned*)pW2b, (int*)pH2, H_DIM, nullptr, nullptr);
    k_fixH<<<H_DIM / 128, 128>>>((const int2*)pz1, (const int*)pnz1,
                                 (const unsigned*)pW2b, (int*)pH2, H_DIM);
    k_stats_i<<<H_DIM / 32, 1024>>>((const int*)pH2);
    k_pack_i<<<(R_ROWS * KW * 32) / 256, 256>>>((const int*)pH2, (unsigned*)pB2,
                                                g2, b2, (int*)pnz2, (int2*)pz2);

    // layer 3
    k_bingemm<false><<<dim3(H_DIM / 64, R_ROWS / 64), 256>>>(
        (const unsigned*)pB2, (const unsigned*)pW3b, (int*)pH3, H_DIM, nullptr, nullptr);
    k_fixH<<<H_DIM / 128, 128>>>((const int2*)pz2, (const int*)pnz2,
                                 (const unsigned*)pW3b, (int*)pH3, H_DIM);
    k_stats_i<<<H_DIM / 32, 1024>>>((const int*)pH3);
    k_pack_i<<<(R_ROWS * KW * 32) / 256, 256>>>((const int*)pH3, (unsigned*)pB3,
                                                g3, b3, (int*)pnz3, (int2*)pz3);

    // layer 4: binary GEMM + scale + un-permute into d_out, then zero fix-up
    k_bingemm<true><<<dim3(F_DIM / 64, R_ROWS / 64), 256>>>(
        (const unsigned*)pB3, (const unsigned*)pW4b, nullptr, F_DIM, scale, out);
    k_fixOut<<<F_DIM / 128, 128>>>((const int2*)pz3, (const int*)pnz3,
                                   (const unsigned*)pW4b, out, scale);
}

// round 15
// speedup vs baseline: 1.1052x; 1.1052x over previous
#include <cuda_runtime.h>
#include <cstdint>

// Problem: BinarizedNetwork_91139206021329   (bit-exact vs XLA:CPU reference)
// Layer 1: fp32 STRICT sequential-k FMA GEMM (scalar FFMA, prefetch-overlapped,
//          ~116 regs -> 2 blocks/SM; R13's f32x2 variant regressed: 135+ regs,
//          1 block/SM, +50% LDS). STRICT sequential-row mean.
// Layers 2..4: exact integer binary GEMMs (XOR+popcount) with exact
//          jnp.sign(0)=0 handling via zero-lists + fix-up kernels.

#define N_IMG   16
#define F_DIM   512
#define T_DIM   512
#define H_DIM   2048
#define R_ROWS  8192          // N_IMG * T_DIM
#define KW      64            // H_DIM / 32 packed words
#define KWPAD   68            // padded smem row stride (words)
#define EPS_BN  1e-5f
#define MAXZ    1024          // max tracked sign(0) events per boundary

// ------------------------- scratch (device globals; no allocation) ----------
__device__ float    g_H1 [R_ROWS * H_DIM];    // layer-1 pre-BN activations
__device__ int      g_H2 [R_ROWS * H_DIM];
__device__ int      g_H3 [R_ROWS * H_DIM];
__device__ unsigned g_B1 [R_ROWS * KW];
__device__ unsigned g_B2 [R_ROWS * KW];
__device__ unsigned g_B3 [R_ROWS * KW];
__device__ unsigned g_W2b[H_DIM * KW];
__device__ unsigned g_W3b[H_DIM * KW];
__device__ unsigned g_W4b[F_DIM * KW];
__device__ float    g_mu [H_DIM];
__device__ float    g_rs [H_DIM];
__device__ int      g_nz1, g_nz2, g_nz3;      // zero-event counters
__device__ int2     g_z1[MAXZ], g_z2[MAXZ], g_z3[MAXZ];   // (row, col)

// ------------------------- misc ----------------------------------------------
__global__ void k_reset() { g_nz1 = 0; g_nz2 = 0; g_nz3 = 0; }

// pack one 32-float chunk per warp: bit set <=> weight < 0 (sign == -1)
__global__ void k_pack_w(const float* __restrict__ W, unsigned* __restrict__ B,
                         int total_words) {
    int gw   = (blockIdx.x * blockDim.x + threadIdx.x) >> 5;
    int lane = threadIdx.x & 31;
    if (gw < total_words) {
        float w = W[gw * 32 + lane];
        unsigned bits = __ballot_sync(0xffffffffu, w < 0.f);
        if (lane == 0) B[gw] = bits;
    }
}

__device__ __forceinline__ float signf_ref(float w) {
    return (w > 0.f) ? 1.f : ((w < 0.f) ? -1.f : 0.f);
}

// ------------------------- layer-1 fp32 GEMM --------------------------------
// H1[r, j] = sum_f x[n, f, t] * sign(W1[j, f]),  r = n*512 + t
// ONE accumulator per output, pure fmaf, k strictly ascending 0..511 (bit-exact
// vs Eigen/XLA-CPU). Next K-tile prefetched into registers during compute.
// sign(W1) applied at smem staging (no separate pass / scratch array).
__global__ __launch_bounds__(256) void k_gemm1(const float* __restrict__ x,
                                               const float* __restrict__ W1) {
    __shared__ float As[16][128];
    __shared__ float Bs[16][128];
    const int tid = threadIdx.x;
    const int bm  = blockIdx.y * 128;
    const int bn  = blockIdx.x * 128;
    const float* xb = x + (bm >> 9) * (F_DIM * T_DIM) + (bm & 511);
    const int tx = tid & 15, ty = tid >> 4;

    // staging assignments (fixed per thread)
    const int sa_k = tid >> 7;           // 0..1
    const int sa_m = tid & 127;
    const int sb_j = tid >> 2;           // 0..63 (two j's: +0, +64)
    const int sb_f = (tid & 3) * 4;

    float  ra[8];
    float4 rb[2];

    // ---- load tile k0 = 0 into regs ----
#pragma unroll
    for (int p = 0; p < 8; p++)
        ra[p] = xb[(sa_k + 2 * p) * T_DIM + sa_m];
#pragma unroll
    for (int p = 0; p < 2; p++)
        rb[p] = *reinterpret_cast<const float4*>(
            &W1[(size_t)(bn + sb_j + 64 * p) * F_DIM + sb_f]);

    // ---- store tile 0 ----
#pragma unroll
    for (int p = 0; p < 8; p++) As[sa_k + 2 * p][sa_m] = ra[p];
#pragma unroll
    for (int p = 0; p < 2; p++) {
        int j = sb_j + 64 * p;
        Bs[sb_f + 0][j] = signf_ref(rb[p].x);
        Bs[sb_f + 1][j] = signf_ref(rb[p].y);
        Bs[sb_f + 2][j] = signf_ref(rb[p].z);
        Bs[sb_f + 3][j] = signf_ref(rb[p].w);
    }
    __syncthreads();

    float acc[8][8];
#pragma unroll
    for (int i = 0; i < 8; i++)
#pragma unroll
        for (int j = 0; j < 8; j++) acc[i][j] = 0.f;

    for (int k0 = 16; k0 <= F_DIM; k0 += 16) {
        const bool more = (k0 < F_DIM);
        if (more) {   // prefetch next tile (overlaps compute below)
#pragma unroll
            for (int p = 0; p < 8; p++)
                ra[p] = xb[(k0 + sa_k + 2 * p) * T_DIM + sa_m];
#pragma unroll
            for (int p = 0; p < 2; p++)
                rb[p] = *reinterpret_cast<const float4*>(
                    &W1[(size_t)(bn + sb_j + 64 * p) * F_DIM + k0 + sb_f]);
        }
        // compute current tile (k ascending within tile; tiles ascending)
#pragma unroll
        for (int kk = 0; kk < 16; kk++) {
            float a[8], b[8];
#pragma unroll
            for (int i = 0; i < 8; i++) a[i] = As[kk][ty * 8 + i];
#pragma unroll
            for (int j = 0; j < 8; j++) b[j] = Bs[kk][tx * 8 + j];
#pragma unroll
            for (int i = 0; i < 8; i++)
#pragma unroll
                for (int j = 0; j < 8; j++) acc[i][j] = fmaf(a[i], b[j], acc[i][j]);
        }
        if (more) {
            __syncthreads();
#pragma unroll
            for (int p = 0; p < 8; p++) As[sa_k + 2 * p][sa_m] = ra[p];
#pragma unroll
            for (int p = 0; p < 2; p++) {
                int j = sb_j + 64 * p;
                Bs[sb_f + 0][j] = signf_ref(rb[p].x);
                Bs[sb_f + 1][j] = signf_ref(rb[p].y);
                Bs[sb_f + 2][j] = signf_ref(rb[p].z);
                Bs[sb_f + 3][j] = signf_ref(rb[p].w);
            }
            __syncthreads();
        }
    }

#pragma unroll
    for (int i = 0; i < 8; i++) {
        float4* dst = reinterpret_cast<float4*>(
            &g_H1[(size_t)(bm + ty * 8 + i) * H_DIM + bn + tx * 8]);
        dst[0] = make_float4(acc[i][0], acc[i][1], acc[i][2], acc[i][3]);
        dst[1] = make_float4(acc[i][4], acc[i][5], acc[i][6], acc[i][7]);
    }
}

// ------------------------- BN stats (layer 1, fp32) ---------------------------
// STRICT sequential accumulation over rows 0..8191 per column (bit-matches
// XLA:CPU column-reduce). 64 blocks x 32 threads spreads across more SMs;
// per-thread arithmetic unchanged.
__global__ __launch_bounds__(32) void k_stats_f_seq() {
    int c = blockIdx.x * blockDim.x + threadIdx.x;   // 0..2047
    float s = 0.f, q = 0.f;
    for (int r = 0; r < R_ROWS; r++) {
        float h = g_H1[(size_t)r * H_DIM + c];
        s += h;
        q = fmaf(h, h, q);
    }
    float mu  = s * (1.0f / R_ROWS);
    float var = q * (1.0f / R_ROWS) - mu * mu;
    g_mu[c] = mu;
    g_rs[c] = rsqrtf(fmaxf(var, 0.f) + EPS_BN);
}

// integer activations: exact sums (|partial| <= 2^24) -> mu bit-exact.
__global__ __launch_bounds__(1024) void k_stats_i(const int* __restrict__ H) {
    __shared__ int       s_sum[1024];
    __shared__ long long s_sq [1024];
    const int tid = threadIdx.x;
    const int c  = blockIdx.x * 32 + (tid & 31);
    const int ry = tid >> 5;
    int s = 0; long long q = 0;
    for (int i = 0; i < R_ROWS / 32; i++) {
        int h = H[(size_t)(i * 32 + ry) * H_DIM + c];
        s += h; q += (long long)h * h;
    }
    s_sum[tid] = s; s_sq[tid] = q;
    __syncthreads();
    if (ry == 0) {
        for (int k = 1; k < 32; k++) {
            s += s_sum[tid + 32 * k];
            q += s_sq [tid + 32 * k];
        }
        float  mu  = (float)s * (1.0f / R_ROWS);
        double var = (double)q * (1.0 / R_ROWS) - (double)mu * (double)mu;
        g_mu[c] = mu;
        g_rs[c] = rsqrtf(fmaxf((float)var, 0.f) + EPS_BN);
    }
}

// ------------------------- BN + sign + bit-pack (+ zero detect) ---------------
__global__ __launch_bounds__(256) void k_pack_f(unsigned* __restrict__ B,
        const float* __restrict__ gg, const float* __restrict__ bb,
        int* __restrict__ nz, int2* __restrict__ zl) {
    int gw   = (blockIdx.x * blockDim.x + threadIdx.x) >> 5;
    int lane = threadIdx.x & 31;
    if (gw < R_ROWS * KW) {
        int c = (gw & 63) * 32 + lane;
        float h = g_H1[(size_t)(gw >> 6) * H_DIM + c];
        float v = fmaf(gg[c], (h - g_mu[c]) * g_rs[c], bb[c]);
        unsigned bits = __ballot_sync(0xffffffffu, v < 0.f);
        if (v == 0.0f) {
            int idx = atomicAdd(nz, 1);
            if (idx < MAXZ) zl[idx] = make_int2(gw >> 6, c);
        }
        if (lane == 0) B[gw] = bits;
    }
}

__global__ __launch_bounds__(256) void k_pack_i(const int* __restrict__ H,
        unsigned* __restrict__ B,
        const float* __restrict__ gg, const float* __restrict__ bb,
        int* __restrict__ nz, int2* __restrict__ zl) {
    int gw   = (blockIdx.x * blockDim.x + threadIdx.x) >> 5;
    int lane = threadIdx.x & 31;
    if (gw < R_ROWS * KW) {
        int c = (gw & 63) * 32 + lane;
        float h = (float)H[(size_t)(gw >> 6) * H_DIM + c];
        float v = fmaf(gg[c], (h - g_mu[c]) * g_rs[c], bb[c]);
        unsigned bits = __ballot_sync(0xffffffffu, v < 0.f);
        if (v == 0.0f) {
            int idx = atomicAdd(nz, 1);
            if (idx < MAXZ) zl[idx] = make_int2(gw >> 6, c);
        }
        if (lane == 0) B[gw] = bits;
    }
}

// ------------------------- zero fix-ups ---------------------------------------
// A zero at (r, p) was packed as +1; true contribution is 0:
// H[r][o] += (w_bit ? +1 : -1). Exact integers; order-free.
__global__ __launch_bounds__(128) void k_fixH(const int2* __restrict__ zl,
        const int* __restrict__ nz, const unsigned* __restrict__ Wb,
        int* __restrict__ H, int Ncols) {
    int o = blockIdx.x * blockDim.x + threadIdx.x;
    if (o >= Ncols) return;
    int n = *nz; if (n > MAXZ) n = MAXZ;
    for (int i = 0; i < n; i++) {
        int r = zl[i].x, p = zl[i].y;
        unsigned w = Wb[(size_t)o * KW + (p >> 5)];
        H[(size_t)r * Ncols + o] += ((w >> (p & 31)) & 1) ? 1 : -1;
    }
}

__global__ __launch_bounds__(128) void k_fixOut(const int2* __restrict__ zl,
        const int* __restrict__ nz, const unsigned* __restrict__ Wb,
        float* __restrict__ out, const float* __restrict__ scale) {
    int o = blockIdx.x * blockDim.x + threadIdx.x;
    if (o >= F_DIM) return;
    int n = *nz; if (n > MAXZ) n = MAXZ;
    for (int i = 0; i < n; i++) {
        int r = zl[i].x, p = zl[i].y;
        int nimg = r >> 9, t = r & 511;
        unsigned w = Wb[(size_t)o * KW + (p >> 5)];
        float d = (((w >> (p & 31)) & 1) ? 1.f : -1.f) * scale[o];
        out[(size_t)nimg * (F_DIM * T_DIM) + (size_t)o * T_DIM + t] += d;
    }
}

// ------------------------- binary GEMM (popcount) ----------------------------
// dot(K=2048) = 2048 - 2*popc(a XOR b). 64x64 tile, full K staged in smem.
template <bool FINAL>
__global__ __launch_bounds__(256) void k_bingemm(
        const unsigned* __restrict__ A, const unsigned* __restrict__ Wb,
        int* __restrict__ Hout, int Ncols,
        const float* __restrict__ scale, float* __restrict__ out) {
    __shared__ unsigned As[64][KWPAD];
    __shared__ unsigned Bs[64][KWPAD];
    const int tid = threadIdx.x;
    const int bm  = blockIdx.y * 64;
    const int bn  = blockIdx.x * 64;

    {
        int m = tid >> 2;
        int q = tid & 3;
        const uint4* srcA = reinterpret_cast<const uint4*>(A  + (size_t)(bm + m) * KW);
        const uint4* srcB = reinterpret_cast<const uint4*>(Wb + (size_t)(bn + m) * KW);
#pragma unroll
        for (int p = 0; p < 4; p++) {
            uint4 v = srcA[q + 4 * p];
            int w = (q + 4 * p) * 4;
            As[w + 0][m] = v.x; As[w + 1][m] = v.y;
            As[w + 2][m] = v.z; As[w + 3][m] = v.w;
        }
#pragma unroll
        for (int p = 0; p < 4; p++) {
            uint4 v = srcB[q + 4 * p];
            int w = (q + 4 * p) * 4;
            Bs[w + 0][m] = v.x; Bs[w + 1][m] = v.y;
            Bs[w + 2][m] = v.z; Bs[w + 3][m] = v.w;
        }
    }
    __syncthreads();

    const int tx = tid & 15, ty = tid >> 4;
    const int m0 = ty * 4, n0 = tx * 4;
    int acc[4][4];
#pragma unroll
    for (int i = 0; i < 4; i++)
#pragma unroll
        for (int j = 0; j < 4; j++) acc[i][j] = 0;

#pragma unroll 4
    for (int kk = 0; kk < 64; kk += 2) {
        uint4 av0 = *reinterpret_cast<const uint4*>(&As[kk + 0][m0]);
        uint4 bv0 = *reinterpret_cast<const uint4*>(&Bs[kk + 0][n0]);
        uint4 av1 = *reinterpret_cast<const uint4*>(&As[kk + 1][m0]);
        uint4 bv1 = *reinterpret_cast<const uint4*>(&Bs[kk + 1][n0]);
        unsigned a0[4] = {av0.x, av0.y, av0.z, av0.w};
        unsigned b0[4] = {bv0.x, bv0.y, bv0.z, bv0.w};
        unsigned a1[4] = {av1.x, av1.y, av1.z, av1.w};
        unsigned b1[4] = {bv1.x, bv1.y, bv1.z, bv1.w};
#pragma unroll
        for (int i = 0; i < 4; i++)
#pragma unroll
            for (int j = 0; j < 4; j++)
                acc[i][j] += __popc(a0[i] ^ b0[j]) + __popc(a1[i] ^ b1[j]);
    }

    if (!FINAL) {
#pragma unroll
        for (int i = 0; i < 4; i++) {
            int4 v = make_int4(H_DIM - 2 * acc[i][0], H_DIM - 2 * acc[i][1],
                               H_DIM - 2 * acc[i][2], H_DIM - 2 * acc[i][3]);
            *reinterpret_cast<int4*>(
                &Hout[(size_t)(bm + m0 + i) * Ncols + bn + n0]) = v;
        }
    } else {
#pragma unroll
        for (int i = 0; i < 4; i++) {
            int r = bm + m0 + i;
            int nimg = r >> 9, t = r & 511;
#pragma unroll
            for (int j = 0; j < 4; j++) {
                int o = bn + n0 + j;
                out[(size_t)nimg * (F_DIM * T_DIM) + (size_t)o * T_DIM + t] =
                    (float)(H_DIM - 2 * acc[i][j]) * scale[o];
            }
        }
    }
}

// ------------------------- launch --------------------------------------------
extern "C" void kernel_launch(void* const* d_in, const int* in_sizes, int n_in,
                              void* d_out, int out_size) {
    (void)in_sizes; (void)n_in; (void)out_size;
    const float* x     = (const float*)d_in[0];
    // d_in[1] = conv_w : dead computation in the reference, skipped.
    const float* W1    = (const float*)d_in[2];
    const float* g1    = (const float*)d_in[3];
    const float* b1    = (const float*)d_in[4];
    const float* W2    = (const float*)d_in[5];
    const float* g2    = (const float*)d_in[6];
    const float* b2    = (const float*)d_in[7];
    const float* W3    = (const float*)d_in[8];
    const float* g3    = (const float*)d_in[9];
    const float* b3    = (const float*)d_in[10];
    const float* W4    = (const float*)d_in[11];
    const float* scale = (const float*)d_in[12];
    float* out = (float*)d_out;

    void *pW2b, *pW3b, *pW4b, *pH2, *pH3, *pB1, *pB2, *pB3;
    void *pnz1, *pnz2, *pnz3, *pz1, *pz2, *pz3;
    cudaGetSymbolAddress(&pW2b, g_W2b);
    cudaGetSymbolAddress(&pW3b, g_W3b);
    cudaGetSymbolAddress(&pW4b, g_W4b);
    cudaGetSymbolAddress(&pH2,  g_H2);
    cudaGetSymbolAddress(&pH3,  g_H3);
    cudaGetSymbolAddress(&pB1,  g_B1);
    cudaGetSymbolAddress(&pB2,  g_B2);
    cudaGetSymbolAddress(&pB3,  g_B3);
    cudaGetSymbolAddress(&pnz1, g_nz1);
    cudaGetSymbolAddress(&pnz2, g_nz2);
    cudaGetSymbolAddress(&pnz3, g_nz3);
    cudaGetSymbolAddress(&pz1,  g_z1);
    cudaGetSymbolAddress(&pz2,  g_z2);
    cudaGetSymbolAddress(&pz3,  g_z3);

    k_reset<<<1, 1>>>();

    // weight prep (sign(W1) folded into k_gemm1's staging)
    k_pack_w<<<(H_DIM * KW * 32) / 256, 256>>>(W2, (unsigned*)pW2b, H_DIM * KW);
    k_pack_w<<<(H_DIM * KW * 32) / 256, 256>>>(W3, (unsigned*)pW3b, H_DIM * KW);
    k_pack_w<<<(F_DIM * KW * 32) / 256, 256>>>(W4, (unsigned*)pW4b, F_DIM * KW);

    // layer 1: fp32 GEMM (scalar, prefetch) -> sequential mean -> sign/pack
    k_gemm1<<<dim3(H_DIM / 128, R_ROWS / 128), 256>>>(x, W1);
    k_stats_f_seq<<<H_DIM / 32, 32>>>();
    k_pack_f<<<(R_ROWS * KW * 32) / 256, 256>>>((unsigned*)pB1, g1, b1,
                                                (int*)pnz1, (int2*)pz1);

    // layer 2
    k_bingemm<false><<<dim3(H_DIM / 64, R_ROWS / 64), 256>>>(
        (const unsigned*)pB1, (const unsigned*)pW2b, (int*)pH2, H_DIM, nullptr, nullptr);
    k_fixH<<<H_DIM / 128, 128>>>((const int2*)pz1, (const int*)pnz1,
                                 (const unsigned*)pW2b, (int*)pH2, H_DIM);
    k_stats_i<<<H_DIM / 32, 1024>>>((const int*)pH2);
    k_pack_i<<<(R_ROWS * KW * 32) / 256, 256>>>((const int*)pH2, (unsigned*)pB2,
                                                g2, b2, (int*)pnz2, (int2*)pz2);

    // layer 3
    k_bingemm<false><<<dim3(H_DIM / 64, R_ROWS / 64), 256>>>(
        (const unsigned*)pB2, (const unsigned*)pW3b, (int*)pH3, H_DIM, nullptr, nullptr);
    k_fixH<<<H_DIM / 128, 128>>>((const int2*)pz2, (const int*)pnz2,
                                 (const unsigned*)pW3b, (int*)pH3, H_DIM);
    k_stats_i<<<H_DIM / 32, 1024>>>((const int*)pH3);
    k_pack_i<<<(R_ROWS * KW * 32) / 256, 256>>>((const int*)pH3, (unsigned*)pB3,
                                                g3, b3, (int*)pnz3, (int2*)pz3);

    // layer 4: binary GEMM + scale + un-permute into d_out, then zero fix-up
    k_bingemm<true><<<dim3(F_DIM / 64, R_ROWS / 64), 256>>>(
        (const unsigned*)pB3, (const unsigned*)pW4b, nullptr, F_DIM, scale, out);
    k_fixOut<<<F_DIM / 128, 128>>>((const int2*)pz3, (const int*)pnz3,
                                   (const unsigned*)pW4b, out, scale);
}